// round 2
// baseline (speedup 1.0000x reference)
#include <cuda_runtime.h>
#include <cuda_fp16.h>
#include <cstdint>
#include <cstddef>

#define HID 1024
#define BAT 512
#define NL  2
#define TT  32

// ---------------- device scratch (allocation-free rule: __device__ globals) ---
__device__ __half g_Wc[(size_t)NL * 4 * HID * 2 * HID];   // [l][4H][2H] fp16, K-concat of W_ih|W_hh
__device__ __half g_thW[(size_t)2 * HID * HID];           // [2H][H] fp16
__device__ __half g_z16[(size_t)BAT * HID];               // fp16(z)
__device__ __half g_x0[(size_t)BAT * HID];                // broadcast init_emb
__device__ __half g_h[NL][(size_t)BAT * HID];             // fp16 hidden per layer
__device__ float  g_c[NL][(size_t)BAT * HID];             // fp32 cell per layer
__device__ float  g_gates[(size_t)BAT * 4 * HID];         // fp32 pre-activation gates

// ---------------- helpers -----------------------------------------------------
__device__ __forceinline__ uint32_t smem_u32(const void* p) {
    return (uint32_t)__cvta_generic_to_shared(p);
}
__device__ __forceinline__ void cp16(uint32_t s, const void* g) {
    asm volatile("cp.async.cg.shared.global [%0], [%1], 16;\n" :: "r"(s), "l"(g));
}
__device__ __forceinline__ void mma16816(float* d, const uint32_t* a, const uint32_t* b) {
    asm volatile(
        "mma.sync.aligned.m16n8k16.row.col.f32.f16.f16.f32 "
        "{%0,%1,%2,%3}, {%4,%5,%6,%7}, {%8,%9}, {%0,%1,%2,%3};\n"
        : "+f"(d[0]), "+f"(d[1]), "+f"(d[2]), "+f"(d[3])
        : "r"(a[0]), "r"(a[1]), "r"(a[2]), "r"(a[3]), "r"(b[0]), "r"(b[1]));
}
// smem tile: 128 rows x 32 halves (64B rows). Two rows share one 128B line.
// chunk-of-16B swizzle: line = r>>1, in-line chunk = ((r&1)*4 + c) ^ (line&7)
__device__ __forceinline__ int swz(int r, int kcol) {   // kcol in halves [0,32)
    int c = kcol >> 3, off = kcol & 7;
    int line = r >> 1;
    int ch = (((r & 1) << 2) | c) ^ (line & 7);
    return line * 64 + ch * 8 + off;
}

// ---------------- conversion kernels ------------------------------------------
__global__ void convert_w_kernel(const float* __restrict__ Wih, const float* __restrict__ Whh) {
    size_t total = (size_t)NL * 4 * HID * 2 * HID;
    for (size_t idx = (size_t)blockIdx.x * blockDim.x + threadIdx.x; idx < total;
         idx += (size_t)gridDim.x * blockDim.x) {
        int k = (int)(idx & (2 * HID - 1));
        size_t ln = idx >> 11;                 // l*4H + n
        float v = (k < HID) ? Wih[ln * HID + k] : Whh[ln * HID + (k - HID)];
        g_Wc[idx] = __float2half(v);
    }
}
__global__ void convert_misc_kernel(const float* __restrict__ z, const float* __restrict__ thW,
                                    const float* __restrict__ emb) {
    int total = 2 * HID * HID;                 // biggest range
    for (int idx = blockIdx.x * blockDim.x + threadIdx.x; idx < total;
         idx += gridDim.x * blockDim.x) {
        g_thW[idx] = __float2half(thW[idx]);
        if (idx < BAT * HID) {
            g_z16[idx] = __float2half(z[idx]);
            g_x0[idx]  = __float2half(emb[idx & (HID - 1)]);
        }
        if (idx < NL * BAT * HID) ((float*)g_c)[idx] = 0.f;
    }
}

// ---------------- GEMM: C[512,N] = [A0|A1][512,K] @ Bw[N,K]^T -----------------
// EPI 0: write raw fp32 accumulators to outF[512,N]
// EPI 1: write fp16 tanh(acc + bias[col]) to outH with col -> (l = col>>10, j = col&1023)
template<int EPI>
__global__ void __launch_bounds__(256)
gemm_kernel(const __half* __restrict__ A0, const __half* __restrict__ A1,
            const __half* __restrict__ Bw, const float* __restrict__ bias,
            float* __restrict__ outF, __half* __restrict__ outH,
            int N, int K)
{
    __shared__ __half sm[2][2][128 * 32];      // [stage][A/B] 32 KB total
    const int tid  = threadIdx.x;
    const int warp = tid >> 5, lane = tid & 31;
    const int g = lane >> 2, tig = lane & 3;
    const int wm = warp & 1, wn = warp >> 1;   // 2 x 4 warp grid, warp tile 64x32
    const int bm = blockIdx.y * 128, bn = blockIdx.x * 128;

    float acc[4][4][4];
    #pragma unroll
    for (int a = 0; a < 4; a++)
        #pragma unroll
        for (int b = 0; b < 4; b++)
            #pragma unroll
            for (int d = 0; d < 4; d++) acc[a][b][d] = 0.f;

    const int KT = K >> 5;

    auto load_stage = [&](int st, int kt) {
        int k0 = kt << 5;
        const __half* As; int ks;
        if (k0 < HID) { As = A0; ks = k0; } else { As = A1; ks = k0 - HID; }
        #pragma unroll
        for (int i = 0; i < 2; i++) {
            int idx = tid + i * 256;
            int r = idx >> 2, c = idx & 3;
            cp16(smem_u32(&sm[st][0][swz(r, c << 3)]),
                 As + (size_t)(bm + r) * HID + ks + (c << 3));
        }
        #pragma unroll
        for (int i = 0; i < 2; i++) {
            int idx = tid + i * 256;
            int r = idx >> 2, c = idx & 3;
            cp16(smem_u32(&sm[st][1][swz(r, c << 3)]),
                 Bw + (size_t)(bn + r) * K + k0 + (c << 3));
        }
    };

    load_stage(0, 0);
    asm volatile("cp.async.commit_group;\n");

    for (int kt = 0; kt < KT; kt++) {
        int cur = kt & 1;
        if (kt + 1 < KT) {
            load_stage(cur ^ 1, kt + 1);
            asm volatile("cp.async.commit_group;\n");
            asm volatile("cp.async.wait_group 1;\n");
        } else {
            asm volatile("cp.async.wait_group 0;\n");
        }
        __syncthreads();

        const __half* sA = sm[cur][0];
        const __half* sB = sm[cur][1];
        #pragma unroll
        for (int s = 0; s < 2; s++) {
            int kk = s << 4;
            uint32_t af[4][4], bf[4][2];
            #pragma unroll
            for (int mt = 0; mt < 4; mt++) {
                int r0 = wm * 64 + mt * 16 + g;
                af[mt][0] = *(const uint32_t*)(sA + swz(r0,     kk +     2 * tig));
                af[mt][1] = *(const uint32_t*)(sA + swz(r0 + 8, kk +     2 * tig));
                af[mt][2] = *(const uint32_t*)(sA + swz(r0,     kk + 8 + 2 * tig));
                af[mt][3] = *(const uint32_t*)(sA + swz(r0 + 8, kk + 8 + 2 * tig));
            }
            #pragma unroll
            for (int nt = 0; nt < 4; nt++) {
                int n = wn * 32 + nt * 8 + g;
                bf[nt][0] = *(const uint32_t*)(sB + swz(n, kk +     2 * tig));
                bf[nt][1] = *(const uint32_t*)(sB + swz(n, kk + 8 + 2 * tig));
            }
            #pragma unroll
            for (int mt = 0; mt < 4; mt++)
                #pragma unroll
                for (int nt = 0; nt < 4; nt++)
                    mma16816(acc[mt][nt], af[mt], bf[nt]);
        }
        __syncthreads();
    }

    // epilogue
    #pragma unroll
    for (int mt = 0; mt < 4; mt++) {
        int r0 = bm + wm * 64 + mt * 16 + g;
        #pragma unroll
        for (int nt = 0; nt < 4; nt++) {
            int col = bn + wn * 32 + nt * 8 + 2 * tig;
            if (EPI == 0) {
                *(float2*)(&outF[(size_t)r0 * N + col])       = make_float2(acc[mt][nt][0], acc[mt][nt][1]);
                *(float2*)(&outF[(size_t)(r0 + 8) * N + col]) = make_float2(acc[mt][nt][2], acc[mt][nt][3]);
            } else {
                float b0 = bias[col], b1 = bias[col + 1];
                int l = col >> 10, j = col & (HID - 1);
                __half2 v0 = __floats2half2_rn(tanhf(acc[mt][nt][0] + b0), tanhf(acc[mt][nt][1] + b1));
                __half2 v1 = __floats2half2_rn(tanhf(acc[mt][nt][2] + b0), tanhf(acc[mt][nt][3] + b1));
                *(__half2*)(&outH[(size_t)l * (BAT * HID) + (size_t)r0 * HID + j])       = v0;
                *(__half2*)(&outH[(size_t)l * (BAT * HID) + (size_t)(r0 + 8) * HID + j]) = v1;
            }
        }
    }
}

// ---------------- LSTM cell elementwise ---------------------------------------
__device__ __forceinline__ float sigf(float x) { return 1.f / (1.f + __expf(-x)); }

__global__ void lstm_cell_kernel(const float* __restrict__ gates,
                                 const float* __restrict__ bih, const float* __restrict__ bhh,
                                 float* __restrict__ c, __half* __restrict__ hout,
                                 float* __restrict__ yout)
{
    int idx = blockIdx.x * blockDim.x + threadIdx.x;   // over BAT*HID
    int b = idx >> 10, j = idx & (HID - 1);
    const float* gb = gates + (size_t)b * 4 * HID;
    float ig = gb[j]           + bih[j]           + bhh[j];
    float fg = gb[HID + j]     + bih[HID + j]     + bhh[HID + j];
    float gg = gb[2 * HID + j] + bih[2 * HID + j] + bhh[2 * HID + j];
    float og = gb[3 * HID + j] + bih[3 * HID + j] + bhh[3 * HID + j];
    float cn = sigf(fg) * c[idx] + sigf(ig) * tanhf(gg);
    float hn = sigf(og) * tanhf(cn);
    c[idx] = cn;
    hout[idx] = __float2half(hn);
    if (yout) yout[idx] = hn;
}

// ---------------- launch -------------------------------------------------------
extern "C" void kernel_launch(void* const* d_in, const int* in_sizes, int n_in,
                              void* d_out, int out_size)
{
    const float* z    = (const float*)d_in[0];
    const float* thW  = (const float*)d_in[1];
    const float* thb  = (const float*)d_in[2];
    const float* emb  = (const float*)d_in[3];
    const float* Wih  = (const float*)d_in[4];
    const float* Whh  = (const float*)d_in[5];
    const float* bih  = (const float*)d_in[6];
    const float* bhh  = (const float*)d_in[7];
    float* out = (float*)d_out;

    __half *Wc, *thWc, *z16, *x0, *h;
    float *c, *gates;
    cudaGetSymbolAddress((void**)&Wc,    g_Wc);
    cudaGetSymbolAddress((void**)&thWc,  g_thW);
    cudaGetSymbolAddress((void**)&z16,   g_z16);
    cudaGetSymbolAddress((void**)&x0,    g_x0);
    cudaGetSymbolAddress((void**)&h,     g_h);
    cudaGetSymbolAddress((void**)&c,     g_c);
    cudaGetSymbolAddress((void**)&gates, g_gates);

    convert_w_kernel<<<1024, 256>>>(Wih, Whh);
    convert_misc_kernel<<<1024, 256>>>(z, thW, emb);

    // h0 = tanh(z @ to_h_W^T + to_h_b)  -> g_h[l][b][j], c0 already zeroed
    gemm_kernel<1><<<dim3((2 * HID) / 128, BAT / 128), 256>>>(
        z16, z16, thWc, thb, nullptr, h, 2 * HID, HID);

    for (int t = 0; t < TT; t++) {
        for (int l = 0; l < NL; l++) {
            const __half* A0 = (l == 0) ? (t == 0 ? x0 : h + (size_t)1 * BAT * HID)
                                        : h;                         // layer0 input / layer1 input
            const __half* A1 = h + (size_t)l * BAT * HID;            // recurrent h
            gemm_kernel<0><<<dim3((4 * HID) / 128, BAT / 128), 256>>>(
                A0, A1, Wc + (size_t)l * 4 * HID * 2 * HID, nullptr, gates, nullptr,
                4 * HID, 2 * HID);
            lstm_cell_kernel<<<(BAT * HID) / 256, 256>>>(
                gates, bih + l * 4 * HID, bhh + l * 4 * HID,
                c + (size_t)l * BAT * HID, h + (size_t)l * BAT * HID,
                (l == NL - 1) ? out + (size_t)t * BAT * HID : nullptr);
        }
    }
}

// round 4
// speedup vs baseline: 1.0110x; 1.0110x over previous
#include <cuda_runtime.h>
#include <cuda_fp16.h>
#include <cstdint>
#include <cstddef>

#define HID 1024
#define BAT 512
#define NL  2
#define TT  32

// ---------------- device scratch ----------------
__device__ __half g_Wc[(size_t)NL * 4 * HID * 2 * HID];  // [l][np][k] gate-interleaved, K-concat
__device__ __half g_thW[(size_t)2 * HID * HID];
__device__ float  g_biasc[NL * 4 * HID];                 // b_ih+b_hh, gate-interleaved
__device__ __half g_z16[(size_t)BAT * HID];
__device__ __half g_x0[(size_t)BAT * HID];
__device__ __half g_h[NL * 2][(size_t)BAT * HID];        // ping-pong per layer
__device__ float  g_c[NL][(size_t)BAT * HID];

// ---------------- helpers ----------------
__device__ __forceinline__ uint32_t smem_u32(const void* p) {
    return (uint32_t)__cvta_generic_to_shared(p);
}
__device__ __forceinline__ void cp16(uint32_t s, const void* g) {
    asm volatile("cp.async.cg.shared.global [%0], [%1], 16;\n" :: "r"(s), "l"(g));
}
__device__ __forceinline__ void mma16816(float* d, const uint32_t* a, const uint32_t* b) {
    asm volatile(
        "mma.sync.aligned.m16n8k16.row.col.f32.f16.f16.f32 "
        "{%0,%1,%2,%3}, {%4,%5,%6,%7}, {%8,%9}, {%0,%1,%2,%3};\n"
        : "+f"(d[0]), "+f"(d[1]), "+f"(d[2]), "+f"(d[3])
        : "r"(a[0]), "r"(a[1]), "r"(a[2]), "r"(a[3]), "r"(b[0]), "r"(b[1]));
}
#define LDSM4(r, addr)                                                          \
    asm volatile("ldmatrix.sync.aligned.m8n8.x4.shared.b16 {%0,%1,%2,%3}, [%4];"\
        : "=r"((r)[0]), "=r"((r)[1]), "=r"((r)[2]), "=r"((r)[3]) : "r"(addr))

// smem tile: 128 rows x 32 halves (64B rows). Two rows share one 128B line.
__device__ __forceinline__ int swz(int r, int kcol) {   // kcol in halves [0,32)
    int c = kcol >> 3, off = kcol & 7;
    int line = r >> 1;
    int ch = (((r & 1) << 2) | c) ^ (line & 7);
    return line * 64 + ch * 8 + off;
}

__device__ __forceinline__ float sigf(float x) {
    return __fdividef(1.f, 1.f + __expf(-x));
}
__device__ __forceinline__ float tanhe(float x) {       // exact 2*sig(2x)-1
    return __fdividef(2.f, 1.f + __expf(-2.f * x)) - 1.f;
}

// ---------------- conversion kernels ----------------
// gate-interleaved layout: np = 16*(u>>2) + 2*(u&3) + gofs, gofs = {i:0, f:1, g:8, o:9}
__global__ void convert_w_kernel(const float* __restrict__ Wih, const float* __restrict__ Whh) {
    size_t total = (size_t)NL * 4 * HID * 2 * HID;
    for (size_t idx = (size_t)blockIdx.x * blockDim.x + threadIdx.x; idx < total;
         idx += (size_t)gridDim.x * blockDim.x) {
        int k  = (int)(idx & (2 * HID - 1));
        int np = (int)((idx >> 11) & 4095);
        int l  = (int)(idx >> 23);
        int within = np & 15, block = np >> 4;
        int gate = ((within & 8) ? 2 : 0) + (within & 1);
        int tig  = (within & 7) >> 1;
        int u = block * 4 + tig;
        size_t ln = (size_t)l * 4 * HID + (size_t)gate * HID + u;
        float v = (k < HID) ? Wih[ln * HID + k] : Whh[ln * HID + (k - HID)];
        g_Wc[idx] = __float2half(v);
    }
}
__global__ void convert_misc_kernel(const float* __restrict__ z, const float* __restrict__ thW,
                                    const float* __restrict__ emb,
                                    const float* __restrict__ bih, const float* __restrict__ bhh) {
    int total = 2 * HID * HID;
    for (int idx = blockIdx.x * blockDim.x + threadIdx.x; idx < total;
         idx += gridDim.x * blockDim.x) {
        g_thW[idx] = __float2half(thW[idx]);
        if (idx < BAT * HID) {
            g_z16[idx] = __float2half(z[idx]);
            g_x0[idx]  = __float2half(emb[idx & (HID - 1)]);
        }
        if (idx < NL * BAT * HID) ((float*)g_c)[idx] = 0.f;
        if (idx < NL * 4 * HID) {
            int l = idx >> 12, np = idx & 4095;
            int within = np & 15, block = np >> 4;
            int gate = ((within & 8) ? 2 : 0) + (within & 1);
            int tig  = (within & 7) >> 1;
            int u = block * 4 + tig;
            int src = l * 4 * HID + gate * HID + u;
            g_biasc[idx] = bih[src] + bhh[src];
        }
    }
}

// ---------------- fused GEMM (+LSTM cell) ----------------
// C[512,N] = [A0|A1][512,K] @ Bw[N,K]^T, tile 128x128, 8 warps (2m x 4n), warp 64x32
// 3-stage cp.async pipeline, ldmatrix fragment loads.
// EPI 0: LSTM cell on gate-interleaved cols -> c (fp32), h (fp16), y (fp32 opt)
// EPI 1: h = tanh(acc + bias[col]), col -> (l = col>>10, j = col&1023)
template<int EPI>
__global__ void __launch_bounds__(256)
lstm_gemm(const __half* __restrict__ A0, const __half* __restrict__ A1,
          const __half* __restrict__ Bw, const float* __restrict__ bias,
          float* __restrict__ cptr, __half* __restrict__ hptr,
          float* __restrict__ yptr, int KT)
{
    __shared__ __half sm[3][2][4096];                    // 48KB: 3 stages x (A 8KB | B 8KB)
    const uint32_t sb = smem_u32(sm);
    const int tid = threadIdx.x, wid = tid >> 5, lane = tid & 31;
    const int g8 = lane >> 2, tig = lane & 3;
    const int wm = wid & 1, wn = wid >> 1;
    const int bm = blockIdx.y * 128, bn = blockIdx.x * 128;
    const int Kh = KT * 32;

    float acc[4][4][4];
    #pragma unroll
    for (int a = 0; a < 4; a++)
        #pragma unroll
        for (int b = 0; b < 4; b++)
            #pragma unroll
            for (int d = 0; d < 4; d++) acc[a][b][d] = 0.f;

    // ldmatrix per-lane byte offsets within a stage
    uint32_t aoff[4][2], boff[2][2];
    {
        int arow = lane & 15, ak = (lane >> 4) * 8;                 // A x4 grouping
        int brow = (lane & 7) + ((lane & 16) >> 1), bk = (lane & 8);// B x4 grouping
        #pragma unroll
        for (int s = 0; s < 2; s++) {
            #pragma unroll
            for (int mt = 0; mt < 4; mt++)
                aoff[mt][s] = 2 * swz(wm * 64 + mt * 16 + arow, s * 16 + ak);
            #pragma unroll
            for (int p = 0; p < 2; p++)
                boff[p][s] = 2 * swz(wn * 32 + p * 16 + brow, s * 16 + bk);
        }
    }

    auto fill = [&](int kt) {
        int s = kt % 3;
        int k0 = kt << 5;
        const __half* Ap; int ks;
        if (k0 < HID) { Ap = A0; ks = k0; } else { Ap = A1; ks = k0 - HID; }
        uint32_t ab = sb + s * 16384, bb = ab + 8192;
        #pragma unroll
        for (int i = 0; i < 2; i++) {
            int idx = tid + i * 256;
            int r = idx >> 2, cc = idx & 3;
            uint32_t off = 2 * swz(r, cc << 3);
            cp16(ab + off, Ap + (size_t)(bm + r) * HID + ks + (cc << 3));
            cp16(bb + off, Bw + (size_t)(bn + r) * Kh + k0 + (cc << 3));
        }
    };

    fill(0); asm volatile("cp.async.commit_group;\n");
    fill(1); asm volatile("cp.async.commit_group;\n");

    for (int kt = 0; kt < KT; kt++) {
        if (kt + 1 < KT) asm volatile("cp.async.wait_group 1;\n");
        else             asm volatile("cp.async.wait_group 0;\n");
        __syncthreads();
        if (kt + 2 < KT) { fill(kt + 2); asm volatile("cp.async.commit_group;\n"); }

        uint32_t abase = sb + (kt % 3) * 16384, bbase = abase + 8192;
        #pragma unroll
        for (int s = 0; s < 2; s++) {
            uint32_t af[4][4], bf[2][4];
            #pragma unroll
            for (int mt = 0; mt < 4; mt++) LDSM4(af[mt], abase + aoff[mt][s]);
            #pragma unroll
            for (int p = 0; p < 2; p++)    LDSM4(bf[p],  bbase + boff[p][s]);
            #pragma unroll
            for (int mt = 0; mt < 4; mt++) {
                #pragma unroll
                for (int p = 0; p < 2; p++) {
                    mma16816(acc[mt][2 * p],     af[mt], &bf[p][0]);
                    mma16816(acc[mt][2 * p + 1], af[mt], &bf[p][2]);
                }
            }
        }
    }

    // ---------------- epilogue ----------------
    if (EPI == 0) {
        #pragma unroll
        for (int p = 0; p < 2; p++) {
            int nb = bn + wn * 32 + p * 16 + 2 * tig;
            float bi = bias[nb], bff = bias[nb + 1], bg = bias[nb + 8], bo = bias[nb + 9];
            int u = (bn >> 2) + wn * 8 + p * 4 + tig;
            #pragma unroll
            for (int mt = 0; mt < 4; mt++) {
                #pragma unroll
                for (int hr = 0; hr < 2; hr++) {
                    int b = bm + wm * 64 + mt * 16 + g8 + hr * 8;
                    int d = hr * 2;
                    float ig = acc[mt][2 * p][d]         + bi;
                    float fg = acc[mt][2 * p][d + 1]     + bff;
                    float gg = acc[mt][2 * p + 1][d]     + bg;
                    float og = acc[mt][2 * p + 1][d + 1] + bo;
                    size_t ci = (size_t)b * HID + u;
                    float cn = sigf(fg) * cptr[ci] + sigf(ig) * tanhe(gg);
                    float hn = sigf(og) * tanhe(cn);
                    cptr[ci] = cn;
                    hptr[ci] = __float2half(hn);
                    if (yptr) yptr[ci] = hn;
                }
            }
        }
    } else {
        #pragma unroll
        for (int mt = 0; mt < 4; mt++) {
            int r0 = bm + wm * 64 + mt * 16 + g8;
            #pragma unroll
            for (int nt = 0; nt < 4; nt++) {
                int col = bn + wn * 32 + nt * 8 + 2 * tig;
                float b0 = bias[col], b1 = bias[col + 1];
                int l2 = col >> 10, j = col & (HID - 1);
                __half2 v0 = __floats2half2_rn(tanhe(acc[mt][nt][0] + b0),
                                               tanhe(acc[mt][nt][1] + b1));
                __half2 v1 = __floats2half2_rn(tanhe(acc[mt][nt][2] + b0),
                                               tanhe(acc[mt][nt][3] + b1));
                size_t lofs = (size_t)l2 * 2 * BAT * HID;   // write ping buffer 0 of layer l2
                *(__half2*)(hptr + lofs + (size_t)r0 * HID + j)       = v0;
                *(__half2*)(hptr + lofs + (size_t)(r0 + 8) * HID + j) = v1;
            }
        }
    }
}

// ---------------- launch ----------------
extern "C" void kernel_launch(void* const* d_in, const int* in_sizes, int n_in,
                              void* d_out, int out_size)
{
    const float* z   = (const float*)d_in[0];
    const float* thW = (const float*)d_in[1];
    const float* thb = (const float*)d_in[2];
    const float* emb = (const float*)d_in[3];
    const float* Wih = (const float*)d_in[4];
    const float* Whh = (const float*)d_in[5];
    const float* bih = (const float*)d_in[6];
    const float* bhh = (const float*)d_in[7];
    float* out = (float*)d_out;

    __half *Wc, *thWc, *z16, *x0, *h;
    float *c, *biasc;
    cudaGetSymbolAddress((void**)&Wc,    g_Wc);
    cudaGetSymbolAddress((void**)&thWc,  g_thW);
    cudaGetSymbolAddress((void**)&z16,   g_z16);
    cudaGetSymbolAddress((void**)&x0,    g_x0);
    cudaGetSymbolAddress((void**)&h,     g_h);
    cudaGetSymbolAddress((void**)&c,     g_c);
    cudaGetSymbolAddress((void**)&biasc, g_biasc);

    auto hb = [&](int l, int p) { return h + ((size_t)l * 2 + p) * BAT * HID; };

    convert_w_kernel<<<1024, 256>>>(Wih, Whh);
    convert_misc_kernel<<<1024, 256>>>(z, thW, emb, bih, bhh);

    // h0 = tanh(z @ to_h_W^T + to_h_b): M=512, N=2048, K=1024 -> buffers hb(l,0)
    lstm_gemm<1><<<dim3(16, 4), 256>>>(z16, z16, thWc, thb, nullptr, h, nullptr, 32);

    for (int t = 0; t < TT; t++) {
        int p = t & 1;
        for (int l = 0; l < NL; l++) {
            const __half* Ain  = (l == 0) ? (t == 0 ? x0 : hb(1, p)) : hb(0, p ^ 1);
            const __half* Arec = hb(l, p);
            lstm_gemm<0><<<dim3(32, 4), 256>>>(
                Ain, Arec,
                Wc + (size_t)l * 4 * HID * 2 * HID,
                biasc + l * 4 * HID,
                c + (size_t)l * BAT * HID,
                hb(l, p ^ 1),
                (l == NL - 1) ? out + (size_t)t * BAT * HID : nullptr,
                64);
        }
    }
}

// round 5
// speedup vs baseline: 1.2653x; 1.2516x over previous
#include <cuda_runtime.h>
#include <cuda_fp16.h>
#include <cstdint>
#include <cstddef>

#define HID 1024
#define BAT 512
#define NL  2
#define TT  32

#define STG_BYTES 32768          // A 16KB + B 16KB (128 rows x 64 halves each)
#define NSTG 3
#define SMEM_BYTES (NSTG * STG_BYTES)

// ---------------- device scratch ----------------
__device__ __half g_Wc[(size_t)NL * 4 * HID * 2 * HID];  // [l][np][k] gate-interleaved, K-concat
__device__ __half g_thW[(size_t)2 * HID * HID];
__device__ float  g_biasc[NL * 4 * HID];
__device__ __half g_z16[(size_t)BAT * HID];
__device__ __half g_x0[(size_t)BAT * HID];
__device__ __half g_h[NL * 2][(size_t)BAT * HID];        // ping-pong per layer
__device__ float  g_c[NL][(size_t)BAT * HID];

// ---------------- helpers ----------------
__device__ __forceinline__ uint32_t smem_u32(const void* p) {
    return (uint32_t)__cvta_generic_to_shared(p);
}
__device__ __forceinline__ void cp16(uint32_t s, const void* g) {
    asm volatile("cp.async.cg.shared.global [%0], [%1], 16;\n" :: "r"(s), "l"(g));
}
__device__ __forceinline__ void mma16816(float* d, const uint32_t* a, const uint32_t* b) {
    asm volatile(
        "mma.sync.aligned.m16n8k16.row.col.f32.f16.f16.f32 "
        "{%0,%1,%2,%3}, {%4,%5,%6,%7}, {%8,%9}, {%0,%1,%2,%3};\n"
        : "+f"(d[0]), "+f"(d[1]), "+f"(d[2]), "+f"(d[3])
        : "r"(a[0]), "r"(a[1]), "r"(a[2]), "r"(a[3]), "r"(b[0]), "r"(b[1]));
}
#define LDSM4(r, addr)                                                          \
    asm volatile("ldmatrix.sync.aligned.m8n8.x4.shared.b16 {%0,%1,%2,%3}, [%4];"\
        : "=r"((r)[0]), "=r"((r)[1]), "=r"((r)[2]), "=r"((r)[3]) : "r"(addr))

// smem tile: 128 rows x 64 halves (128B rows), classic 8-chunk xor swizzle.
// returns HALF index within tile
__device__ __forceinline__ int swz64(int r, int k) {
    return r * 64 + ((((k >> 3) ^ (r & 7)) << 3) | (k & 7));
}

__device__ __forceinline__ float sigf(float x) {
    return __fdividef(1.f, 1.f + __expf(-x));
}
__device__ __forceinline__ float tanhe(float x) {
    return __fdividef(2.f, 1.f + __expf(-2.f * x)) - 1.f;
}

// ---------------- conversion kernels ----------------
// gate-interleaved: np = 16*(u>>2) + 2*(u&3) + gofs, gofs = {i:0, f:1, g:8, o:9}
__global__ void convert_w_kernel(const float* __restrict__ Wih, const float* __restrict__ Whh) {
    size_t total = (size_t)NL * 4 * HID * 2 * HID;
    for (size_t idx = (size_t)blockIdx.x * blockDim.x + threadIdx.x; idx < total;
         idx += (size_t)gridDim.x * blockDim.x) {
        int k  = (int)(idx & (2 * HID - 1));
        int np = (int)((idx >> 11) & 4095);
        int l  = (int)(idx >> 23);
        int within = np & 15, block = np >> 4;
        int gate = ((within & 8) ? 2 : 0) + (within & 1);
        int tig  = (within & 7) >> 1;
        int u = block * 4 + tig;
        size_t ln = (size_t)l * 4 * HID + (size_t)gate * HID + u;
        float v = (k < HID) ? Wih[ln * HID + k] : Whh[ln * HID + (k - HID)];
        g_Wc[idx] = __float2half(v);
    }
}
__global__ void convert_misc_kernel(const float* __restrict__ z, const float* __restrict__ thW,
                                    const float* __restrict__ emb,
                                    const float* __restrict__ bih, const float* __restrict__ bhh) {
    int total = 2 * HID * HID;
    for (int idx = blockIdx.x * blockDim.x + threadIdx.x; idx < total;
         idx += gridDim.x * blockDim.x) {
        g_thW[idx] = __float2half(thW[idx]);
        if (idx < BAT * HID) {
            g_z16[idx] = __float2half(z[idx]);
            g_x0[idx]  = __float2half(emb[idx & (HID - 1)]);
        }
        if (idx < NL * BAT * HID) ((float*)g_c)[idx] = 0.f;
        if (idx < NL * 4 * HID) {
            int l = idx >> 12, np = idx & 4095;
            int within = np & 15, block = np >> 4;
            int gate = ((within & 8) ? 2 : 0) + (within & 1);
            int tig  = (within & 7) >> 1;
            int u = block * 4 + tig;
            int src = l * 4 * HID + gate * HID + u;
            g_biasc[idx] = bih[src] + bhh[src];
        }
    }
}

// ---------------- fused GEMM (+LSTM cell) ----------------
// C[512,N] = [A0|A1][512,K] @ Bw[N,K]^T
// tile 128x128, 16 warps (4m x 4n), warp tile 32x32, k-chunk 64, 3-stage cp.async.
template<int EPI>
__global__ void __launch_bounds__(512)
lstm_gemm(const __half* __restrict__ A0, const __half* __restrict__ A1,
          const __half* __restrict__ Bw, const float* __restrict__ bias,
          float* __restrict__ cptr, __half* __restrict__ hptr,
          float* __restrict__ yptr, int KT)            // KT in 64-half chunks
{
    extern __shared__ __half sm[];
    const uint32_t sb = smem_u32(sm);
    const int tid = threadIdx.x, wid = tid >> 5, lane = tid & 31;
    const int g8 = lane >> 2, tig = lane & 3;
    const int wm = wid & 3, wn = wid >> 2;             // 4 x 4 warp grid
    const int bm = blockIdx.y * 128, bn = blockIdx.x * 128;
    const int Kh = KT * 64;

    float acc[2][4][4];
    #pragma unroll
    for (int a = 0; a < 2; a++)
        #pragma unroll
        for (int b = 0; b < 4; b++)
            #pragma unroll
            for (int d = 0; d < 4; d++) acc[a][b][d] = 0.f;

    // ldmatrix per-lane byte offsets within a stage (4 k-slices of 16)
    uint32_t aoff[2][4], boff[2][4];
    {
        int arow = lane & 15, ak = (lane >> 4) * 8;
        int brow = (lane & 7) + ((lane & 16) >> 1), bk = (lane & 8);
        #pragma unroll
        for (int s = 0; s < 4; s++) {
            #pragma unroll
            for (int mt = 0; mt < 2; mt++)
                aoff[mt][s] = 2 * swz64(wm * 32 + mt * 16 + arow, s * 16 + ak);
            #pragma unroll
            for (int p = 0; p < 2; p++)
                boff[p][s] = 16384 + 2 * swz64(wn * 32 + p * 16 + brow, s * 16 + bk);
        }
    }

    auto fill = [&](int kt) {
        int st = kt % NSTG;
        int k0 = kt << 6;
        const __half* Ap; int ks;
        if (k0 < HID) { Ap = A0; ks = k0; } else { Ap = A1; ks = k0 - HID; }
        uint32_t ab = sb + st * STG_BYTES, bb = ab + 16384;
        #pragma unroll
        for (int i = 0; i < 2; i++) {
            int idx = tid + i * 512;                  // 1024 chunks of 16B
            int r = idx >> 3, c = idx & 7;
            uint32_t off = 2 * swz64(r, c << 3);
            cp16(ab + off, Ap + (size_t)(bm + r) * HID + ks + (c << 3));
            cp16(bb + off, Bw + (size_t)(bn + r) * Kh + k0 + (c << 3));
        }
    };

    fill(0); asm volatile("cp.async.commit_group;\n");
    if (KT > 1) { fill(1); asm volatile("cp.async.commit_group;\n"); }

    for (int kt = 0; kt < KT; kt++) {
        if (kt + 1 < KT) asm volatile("cp.async.wait_group 1;\n");
        else             asm volatile("cp.async.wait_group 0;\n");
        __syncthreads();
        if (kt + 2 < KT) { fill(kt + 2); asm volatile("cp.async.commit_group;\n"); }

        uint32_t base = sb + (kt % NSTG) * STG_BYTES;
        #pragma unroll
        for (int s = 0; s < 4; s++) {
            uint32_t af[2][4], bf[2][4];
            #pragma unroll
            for (int mt = 0; mt < 2; mt++) LDSM4(af[mt], base + aoff[mt][s]);
            #pragma unroll
            for (int p = 0; p < 2; p++)    LDSM4(bf[p],  base + boff[p][s]);
            #pragma unroll
            for (int mt = 0; mt < 2; mt++) {
                #pragma unroll
                for (int p = 0; p < 2; p++) {
                    mma16816(acc[mt][2 * p],     af[mt], &bf[p][0]);
                    mma16816(acc[mt][2 * p + 1], af[mt], &bf[p][2]);
                }
            }
        }
        __syncthreads();
    }

    // ---------------- epilogue ----------------
    if (EPI == 0) {
        #pragma unroll
        for (int p = 0; p < 2; p++) {
            int nb = bn + wn * 32 + p * 16 + 2 * tig;
            float bi = bias[nb], bff = bias[nb + 1], bg = bias[nb + 8], bo = bias[nb + 9];
            int u = (bn >> 2) + wn * 8 + p * 4 + tig;
            #pragma unroll
            for (int mt = 0; mt < 2; mt++) {
                #pragma unroll
                for (int hr = 0; hr < 2; hr++) {
                    int b = bm + wm * 32 + mt * 16 + g8 + hr * 8;
                    int d = hr * 2;
                    float ig = acc[mt][2 * p][d]         + bi;
                    float fg = acc[mt][2 * p][d + 1]     + bff;
                    float gg = acc[mt][2 * p + 1][d]     + bg;
                    float og = acc[mt][2 * p + 1][d + 1] + bo;
                    size_t ci = (size_t)b * HID + u;
                    float cn = sigf(fg) * cptr[ci] + sigf(ig) * tanhe(gg);
                    float hn = sigf(og) * tanhe(cn);
                    cptr[ci] = cn;
                    hptr[ci] = __float2half(hn);
                    if (yptr) yptr[ci] = hn;
                }
            }
        }
    } else {
        #pragma unroll
        for (int mt = 0; mt < 2; mt++) {
            int r0 = bm + wm * 32 + mt * 16 + g8;
            #pragma unroll
            for (int nt = 0; nt < 4; nt++) {
                int col = bn + wn * 32 + nt * 8 + 2 * tig;
                float b0 = bias[col], b1 = bias[col + 1];
                int l2 = col >> 10, j = col & (HID - 1);
                __half2 v0 = __floats2half2_rn(tanhe(acc[mt][nt][0] + b0),
                                               tanhe(acc[mt][nt][1] + b1));
                __half2 v1 = __floats2half2_rn(tanhe(acc[mt][nt][2] + b0),
                                               tanhe(acc[mt][nt][3] + b1));
                size_t lofs = (size_t)l2 * 2 * BAT * HID;   // ping buffer 0 of layer l2
                *(__half2*)(hptr + lofs + (size_t)r0 * HID + j)       = v0;
                *(__half2*)(hptr + lofs + (size_t)(r0 + 8) * HID + j) = v1;
            }
        }
    }
}

// ---------------- launch ----------------
extern "C" void kernel_launch(void* const* d_in, const int* in_sizes, int n_in,
                              void* d_out, int out_size)
{
    const float* z   = (const float*)d_in[0];
    const float* thW = (const float*)d_in[1];
    const float* thb = (const float*)d_in[2];
    const float* emb = (const float*)d_in[3];
    const float* Wih = (const float*)d_in[4];
    const float* Whh = (const float*)d_in[5];
    const float* bih = (const float*)d_in[6];
    const float* bhh = (const float*)d_in[7];
    float* out = (float*)d_out;

    __half *Wc, *thWc, *z16, *x0, *h;
    float *c, *biasc;
    cudaGetSymbolAddress((void**)&Wc,    g_Wc);
    cudaGetSymbolAddress((void**)&thWc,  g_thW);
    cudaGetSymbolAddress((void**)&z16,   g_z16);
    cudaGetSymbolAddress((void**)&x0,    g_x0);
    cudaGetSymbolAddress((void**)&h,     g_h);
    cudaGetSymbolAddress((void**)&c,     g_c);
    cudaGetSymbolAddress((void**)&biasc, g_biasc);

    cudaFuncSetAttribute(lstm_gemm<0>, cudaFuncAttributeMaxDynamicSharedMemorySize, SMEM_BYTES);
    cudaFuncSetAttribute(lstm_gemm<1>, cudaFuncAttributeMaxDynamicSharedMemorySize, SMEM_BYTES);

    auto hb = [&](int l, int p) { return h + ((size_t)l * 2 + p) * BAT * HID; };

    convert_w_kernel<<<1024, 256>>>(Wih, Whh);
    convert_misc_kernel<<<1024, 256>>>(z, thW, emb, bih, bhh);

    // h0 = tanh(z @ to_h_W^T + to_h_b): M=512, N=2048, K=1024 -> ping buffer 0
    lstm_gemm<1><<<dim3(16, 4), 512, SMEM_BYTES>>>(z16, z16, thWc, thb,
                                                   nullptr, h, nullptr, 16);

    for (int t = 0; t < TT; t++) {
        int p = t & 1;
        for (int l = 0; l < NL; l++) {
            const __half* Ain  = (l == 0) ? (t == 0 ? x0 : hb(1, p)) : hb(0, p ^ 1);
            const __half* Arec = hb(l, p);
            lstm_gemm<0><<<dim3(32, 4), 512, SMEM_BYTES>>>(
                Ain, Arec,
                Wc + (size_t)l * 4 * HID * 2 * HID,
                biasc + l * 4 * HID,
                c + (size_t)l * BAT * HID,
                hb(l, p ^ 1),
                (l == NL - 1) ? out + (size_t)t * BAT * HID : nullptr,
                32);
        }
    }
}

// round 6
// speedup vs baseline: 1.4105x; 1.1147x over previous
#include <cuda_runtime.h>
#include <cuda_fp16.h>
#include <cstdint>
#include <cstddef>

#define HID 1024
#define BAT 512
#define NL  2
#define TT  32

#define STG_BYTES 32768          // A 16KB + B 16KB (128 rows x 64 halves each)
#define NSTG 6                   // 6-stage ring = 3 pairs in flight
#define SMEM_BYTES (NSTG * STG_BYTES)

// ---------------- device scratch ----------------
__device__ __half g_Wc[(size_t)NL * 4 * HID * 2 * HID];  // [l][np][k] gate-interleaved, K-concat
__device__ __half g_thW[(size_t)2 * HID * HID];
__device__ float  g_biasc[NL * 4 * HID];
__device__ __half g_z16[(size_t)BAT * HID];
__device__ __half g_x0[(size_t)BAT * HID];
__device__ __half g_h[NL * 2][(size_t)BAT * HID];        // ping-pong per layer
__device__ float  g_c[NL][(size_t)BAT * HID];

// ---------------- helpers ----------------
__device__ __forceinline__ uint32_t smem_u32(const void* p) {
    return (uint32_t)__cvta_generic_to_shared(p);
}
__device__ __forceinline__ void cp16(uint32_t s, const void* g) {
    asm volatile("cp.async.cg.shared.global [%0], [%1], 16;\n" :: "r"(s), "l"(g));
}
__device__ __forceinline__ void mma16816(float* d, const uint32_t* a, const uint32_t* b) {
    asm volatile(
        "mma.sync.aligned.m16n8k16.row.col.f32.f16.f16.f32 "
        "{%0,%1,%2,%3}, {%4,%5,%6,%7}, {%8,%9}, {%0,%1,%2,%3};\n"
        : "+f"(d[0]), "+f"(d[1]), "+f"(d[2]), "+f"(d[3])
        : "r"(a[0]), "r"(a[1]), "r"(a[2]), "r"(a[3]), "r"(b[0]), "r"(b[1]));
}
#define LDSM4(r, addr)                                                          \
    asm volatile("ldmatrix.sync.aligned.m8n8.x4.shared.b16 {%0,%1,%2,%3}, [%4];"\
        : "=r"((r)[0]), "=r"((r)[1]), "=r"((r)[2]), "=r"((r)[3]) : "r"(addr))

// smem tile: 128 rows x 64 halves (128B rows), classic 8-chunk xor swizzle.
__device__ __forceinline__ int swz64(int r, int k) {
    return r * 64 + ((((k >> 3) ^ (r & 7)) << 3) | (k & 7));
}

__device__ __forceinline__ float sigf(float x) {
    return __fdividef(1.f, 1.f + __expf(-x));
}
__device__ __forceinline__ float tanhe(float x) {
    return __fdividef(2.f, 1.f + __expf(-2.f * x)) - 1.f;
}

// ---------------- conversion kernels ----------------
// gate-interleaved: np = 16*(u>>2) + 2*(u&3) + gofs, gofs = {i:0, f:1, g:8, o:9}
__global__ void convert_w_kernel(const float* __restrict__ Wih, const float* __restrict__ Whh) {
    size_t total = (size_t)NL * 4 * HID * 2 * HID;
    for (size_t idx = (size_t)blockIdx.x * blockDim.x + threadIdx.x; idx < total;
         idx += (size_t)gridDim.x * blockDim.x) {
        int k  = (int)(idx & (2 * HID - 1));
        int np = (int)((idx >> 11) & 4095);
        int l  = (int)(idx >> 23);
        int within = np & 15, block = np >> 4;
        int gate = ((within & 8) ? 2 : 0) + (within & 1);
        int tig  = (within & 7) >> 1;
        int u = block * 4 + tig;
        size_t ln = (size_t)l * 4 * HID + (size_t)gate * HID + u;
        float v = (k < HID) ? Wih[ln * HID + k] : Whh[ln * HID + (k - HID)];
        g_Wc[idx] = __float2half(v);
    }
}
__global__ void convert_misc_kernel(const float* __restrict__ z, const float* __restrict__ thW,
                                    const float* __restrict__ emb,
                                    const float* __restrict__ bih, const float* __restrict__ bhh) {
    int total = 2 * HID * HID;
    for (int idx = blockIdx.x * blockDim.x + threadIdx.x; idx < total;
         idx += gridDim.x * blockDim.x) {
        g_thW[idx] = __float2half(thW[idx]);
        if (idx < BAT * HID) {
            g_z16[idx] = __float2half(z[idx]);
            g_x0[idx]  = __float2half(emb[idx & (HID - 1)]);
        }
        if (idx < NL * BAT * HID) ((float*)g_c)[idx] = 0.f;
        if (idx < NL * 4 * HID) {
            int l = idx >> 12, np = idx & 4095;
            int within = np & 15, block = np >> 4;
            int gate = ((within & 8) ? 2 : 0) + (within & 1);
            int tig  = (within & 7) >> 1;
            int u = block * 4 + tig;
            int src = l * 4 * HID + gate * HID + u;
            g_biasc[idx] = bih[src] + bhh[src];
        }
    }
}

// ---------------- fused GEMM (+LSTM cell) ----------------
// C[512,N] = [A0|A1][512,K] @ Bw[N,K]^T
// tile 128x128, 16 warps (4m x 4n), warp tile 32x32.
// 6-stage cp.async ring, ONE barrier per 2 k-tiles (128 halves of K),
// register double-buffered ldmatrix fragments across the 8 k-slices.
template<int EPI>
__global__ void __launch_bounds__(512)
lstm_gemm(const __half* __restrict__ A0, const __half* __restrict__ A1,
          const __half* __restrict__ Bw, const float* __restrict__ bias,
          float* __restrict__ cptr, __half* __restrict__ hptr,
          float* __restrict__ yptr, int KT)            // KT in 64-half chunks (even)
{
    extern __shared__ __half sm[];
    const uint32_t sb = smem_u32(sm);
    const int tid = threadIdx.x, wid = tid >> 5, lane = tid & 31;
    const int g8 = lane >> 2, tig = lane & 3;
    const int wm = wid & 3, wn = wid >> 2;             // 4 x 4 warp grid
    const int bm = blockIdx.y * 128, bn = blockIdx.x * 128;
    const int Kh = KT * 64;
    const int NP = KT >> 1;                            // pairs of k-tiles

    float acc[2][4][4];
    #pragma unroll
    for (int a = 0; a < 2; a++)
        #pragma unroll
        for (int b = 0; b < 4; b++)
            #pragma unroll
            for (int d = 0; d < 4; d++) acc[a][b][d] = 0.f;

    // ldmatrix per-lane byte offsets within a stage (4 k-slices of 16)
    uint32_t aoff[2][4], boff[2][4];
    {
        int arow = lane & 15, ak = (lane >> 4) * 8;
        int brow = (lane & 7) + ((lane & 16) >> 1), bk = (lane & 8);
        #pragma unroll
        for (int s = 0; s < 4; s++) {
            #pragma unroll
            for (int mt = 0; mt < 2; mt++)
                aoff[mt][s] = 2 * swz64(wm * 32 + mt * 16 + arow, s * 16 + ak);
            #pragma unroll
            for (int p = 0; p < 2; p++)
                boff[p][s] = 16384 + 2 * swz64(wn * 32 + p * 16 + brow, s * 16 + bk);
        }
    }

    auto fill = [&](int kt) {
        int st = kt % NSTG;
        int k0 = kt << 6;
        const __half* Ap; int ks;
        if (k0 < HID) { Ap = A0; ks = k0; } else { Ap = A1; ks = k0 - HID; }
        uint32_t ab = sb + st * STG_BYTES, bb = ab + 16384;
        #pragma unroll
        for (int i = 0; i < 2; i++) {
            int idx = tid + i * 512;                  // 1024 chunks of 16B
            int r = idx >> 3, c = idx & 7;
            uint32_t off = 2 * swz64(r, c << 3);
            cp16(ab + off, Ap + (size_t)(bm + r) * HID + ks + (c << 3));
            cp16(bb + off, Bw + (size_t)(bn + r) * Kh + k0 + (c << 3));
        }
    };

    // prefill 2 pairs (4 k-tiles), one commit group per pair
    fill(0); fill(1); asm volatile("cp.async.commit_group;\n");
    if (NP > 1) { fill(2); fill(3); asm volatile("cp.async.commit_group;\n"); }

    for (int i = 0; i < NP; i++) {
        if (i + 1 < NP) asm volatile("cp.async.wait_group 1;\n");
        else            asm volatile("cp.async.wait_group 0;\n");
        __syncthreads();
        if (i + 2 < NP) {
            fill(2 * i + 4); fill(2 * i + 5);
            asm volatile("cp.async.commit_group;\n");
        }

        const uint32_t base0 = sb + ((2 * i) % NSTG) * STG_BYTES;
        const uint32_t base1 = sb + ((2 * i + 1) % NSTG) * STG_BYTES;

        uint32_t af[2][2][4], bf[2][2][4];
        // prime slice 0
        LDSM4(af[0][0], base0 + aoff[0][0]);
        LDSM4(af[0][1], base0 + aoff[1][0]);
        LDSM4(bf[0][0], base0 + boff[0][0]);
        LDSM4(bf[0][1], base0 + boff[1][0]);

        #pragma unroll
        for (int ss = 0; ss < 8; ss++) {
            const int cb = ss & 1, nb = cb ^ 1;
            if (ss < 7) {
                const int ns = ss + 1;
                const uint32_t nbase = (ns < 4) ? base0 : base1;
                const int s4 = ns & 3;
                LDSM4(af[nb][0], nbase + aoff[0][s4]);
                LDSM4(af[nb][1], nbase + aoff[1][s4]);
                LDSM4(bf[nb][0], nbase + boff[0][s4]);
                LDSM4(bf[nb][1], nbase + boff[1][s4]);
            }
            #pragma unroll
            for (int mt = 0; mt < 2; mt++) {
                #pragma unroll
                for (int p = 0; p < 2; p++) {
                    mma16816(acc[mt][2 * p],     af[cb][mt], &bf[cb][p][0]);
                    mma16816(acc[mt][2 * p + 1], af[cb][mt], &bf[cb][p][2]);
                }
            }
        }
    }

    // ---------------- epilogue ----------------
    if (EPI == 0) {
        #pragma unroll
        for (int p = 0; p < 2; p++) {
            int nb = bn + wn * 32 + p * 16 + 2 * tig;
            float bi = bias[nb], bff = bias[nb + 1], bg = bias[nb + 8], bo = bias[nb + 9];
            int u = (bn >> 2) + wn * 8 + p * 4 + tig;
            #pragma unroll
            for (int mt = 0; mt < 2; mt++) {
                #pragma unroll
                for (int hr = 0; hr < 2; hr++) {
                    int b = bm + wm * 32 + mt * 16 + g8 + hr * 8;
                    int d = hr * 2;
                    float ig = acc[mt][2 * p][d]         + bi;
                    float fg = acc[mt][2 * p][d + 1]     + bff;
                    float gg = acc[mt][2 * p + 1][d]     + bg;
                    float og = acc[mt][2 * p + 1][d + 1] + bo;
                    size_t ci = (size_t)b * HID + u;
                    float cn = sigf(fg) * cptr[ci] + sigf(ig) * tanhe(gg);
                    float hn = sigf(og) * tanhe(cn);
                    cptr[ci] = cn;
                    hptr[ci] = __float2half(hn);
                    if (yptr) yptr[ci] = hn;
                }
            }
        }
    } else {
        #pragma unroll
        for (int mt = 0; mt < 2; mt++) {
            int r0 = bm + wm * 32 + mt * 16 + g8;
            #pragma unroll
            for (int nt = 0; nt < 4; nt++) {
                int col = bn + wn * 32 + nt * 8 + 2 * tig;
                float b0 = bias[col], b1 = bias[col + 1];
                int l2 = col >> 10, j = col & (HID - 1);
                __half2 v0 = __floats2half2_rn(tanhe(acc[mt][nt][0] + b0),
                                               tanhe(acc[mt][nt][1] + b1));
                __half2 v1 = __floats2half2_rn(tanhe(acc[mt][nt][2] + b0),
                                               tanhe(acc[mt][nt][3] + b1));
                size_t lofs = (size_t)l2 * 2 * BAT * HID;   // ping buffer 0 of layer l2
                *(__half2*)(hptr + lofs + (size_t)r0 * HID + j)       = v0;
                *(__half2*)(hptr + lofs + (size_t)(r0 + 8) * HID + j) = v1;
            }
        }
    }
}

// ---------------- launch ----------------
extern "C" void kernel_launch(void* const* d_in, const int* in_sizes, int n_in,
                              void* d_out, int out_size)
{
    const float* z   = (const float*)d_in[0];
    const float* thW = (const float*)d_in[1];
    const float* thb = (const float*)d_in[2];
    const float* emb = (const float*)d_in[3];
    const float* Wih = (const float*)d_in[4];
    const float* Whh = (const float*)d_in[5];
    const float* bih = (const float*)d_in[6];
    const float* bhh = (const float*)d_in[7];
    float* out = (float*)d_out;

    __half *Wc, *thWc, *z16, *x0, *h;
    float *c, *biasc;
    cudaGetSymbolAddress((void**)&Wc,    g_Wc);
    cudaGetSymbolAddress((void**)&thWc,  g_thW);
    cudaGetSymbolAddress((void**)&z16,   g_z16);
    cudaGetSymbolAddress((void**)&x0,    g_x0);
    cudaGetSymbolAddress((void**)&h,     g_h);
    cudaGetSymbolAddress((void**)&c,     g_c);
    cudaGetSymbolAddress((void**)&biasc, g_biasc);

    cudaFuncSetAttribute(lstm_gemm<0>, cudaFuncAttributeMaxDynamicSharedMemorySize, SMEM_BYTES);
    cudaFuncSetAttribute(lstm_gemm<1>, cudaFuncAttributeMaxDynamicSharedMemorySize, SMEM_BYTES);

    auto hb = [&](int l, int p) { return h + ((size_t)l * 2 + p) * BAT * HID; };

    convert_w_kernel<<<1024, 256>>>(Wih, Whh);
    convert_misc_kernel<<<1024, 256>>>(z, thW, emb, bih, bhh);

    // h0 = tanh(z @ to_h_W^T + to_h_b): M=512, N=2048, K=1024 -> ping buffer 0
    lstm_gemm<1><<<dim3(16, 4), 512, SMEM_BYTES>>>(z16, z16, thWc, thb,
                                                   nullptr, h, nullptr, 16);

    for (int t = 0; t < TT; t++) {
        int p = t & 1;
        for (int l = 0; l < NL; l++) {
            const __half* Ain  = (l == 0) ? (t == 0 ? x0 : hb(1, p)) : hb(0, p ^ 1);
            const __half* Arec = hb(l, p);
            lstm_gemm<0><<<dim3(32, 4), 512, SMEM_BYTES>>>(
                Ain, Arec,
                Wc + (size_t)l * 4 * HID * 2 * HID,
                biasc + l * 4 * HID,
                c + (size_t)l * BAT * HID,
                hb(l, p ^ 1),
                (l == NL - 1) ? out + (size_t)t * BAT * HID : nullptr,
                32);
        }
    }
}